// round 12
// baseline (speedup 1.0000x reference)
#include <cuda_runtime.h>
#include <math_constants.h>

// Problem constants (fixed by the dataset: n=200,000 nodes, ne=12,800,000 edges)
#define MU_C   1.0f
#define DT_C   0.01f
#define EPS_C  1e-9f
#define N_MAX  262144   // >= 200,000, padded

// Device scratch (no allocations allowed in kernel_launch)
// srcP[j] = { s_j*y_j, c_j*y_j, s_j, c_j }  with s=sin(theta_j), c=cos(theta_j)
// acc[i]  = per-dst sums of srcP over incoming edges (float4 vector atomic)
//
// g_acc lifecycle: zero-initialized at module load; node_final_kernel
// read-and-resets each element, so every kernel_launch call (and every graph
// replay) starts from zeros. Deterministic: same inputs -> same output.
__device__ float4 g_srcP[N_MAX];
__device__ float4 g_acc[N_MAX];

// ---------------------------------------------------------------------------
// Kernel 1: per-node precompute (scalar, 1 node/thread — fastest validated
// form). No acc zeroing here anymore (folded into node_final read-and-reset).
// s = y/r, c = (x+eps)/r with r = sqrt((x+eps)^2 + y^2)  (== sin/cos of atan2)
// ---------------------------------------------------------------------------
__global__ void node_init_kernel(const float* __restrict__ x,
                                 const float* __restrict__ y,
                                 int n) {
    int i = blockIdx.x * blockDim.x + threadIdx.x;
    if (i >= n) return;
    float xi = x[i];
    float yi = y[i];
    float xe = xi + EPS_C;
    float inv = rsqrtf(xe * xe + yi * yi);
    float s = yi * inv;
    float c = xe * inv;
    g_srcP[i] = make_float4(s * yi, c * yi, s, c);
}

// ---------------------------------------------------------------------------
// Kernel 2: edge accumulation over [e0, e1) — five-times-validated form.
// For edge (j=src -> i=dst):  acc[i] += { s_j*y_j, c_j*y_j, s_j, c_j }
// One float4 gather + one float4 vector RED per edge; 4 edges/thread with
// int4 streaming index loads. At the diverged-lane-op / LTS-RMW floor.
// ---------------------------------------------------------------------------
__global__ void edge_kernel(const int* __restrict__ edge_src,
                            const int* __restrict__ edge_dst,
                            int e0, int e1) {
    int t = blockIdx.x * blockDim.x + threadIdx.x;
    int base = e0 + t * 4;
    if (base + 3 < e1) {
        int4 si = __ldcs(reinterpret_cast<const int4*>(edge_src + base));
        int4 di = __ldcs(reinterpret_cast<const int4*>(edge_dst + base));
        float4 p0 = __ldg(&g_srcP[si.x]);
        float4 p1 = __ldg(&g_srcP[si.y]);
        float4 p2 = __ldg(&g_srcP[si.z]);
        float4 p3 = __ldg(&g_srcP[si.w]);
        atomicAdd(&g_acc[di.x], p0);
        atomicAdd(&g_acc[di.y], p1);
        atomicAdd(&g_acc[di.z], p2);
        atomicAdd(&g_acc[di.w], p3);
    } else if (base < e1) {
        for (int e = base; e < e1; e++) {
            float4 p = __ldg(&g_srcP[edge_src[e]]);
            atomicAdd(&g_acc[edge_dst[e]], p);
        }
    }
}

// ---------------------------------------------------------------------------
// Kernel 3: finalize (scalar, 1 node/thread) with acc read-and-reset.
//   cy_i = ha_i * [ c_i*A - s_i*B - y_i*(c_i*C - s_i*D) ],  acc[i]={A,B,C,D}
//   dy   = (MU - r2)*y + w*x ; y_new = y + (dy + cy)*DT
//   angles = clip(amp*y_new + phase + b, -pi/2, pi/2)
// (dx / x_new are dead code: the output depends only on y_new.)
// ---------------------------------------------------------------------------
__global__ void node_final_kernel(const float* __restrict__ x,
                                  const float* __restrict__ y,
                                  const float* __restrict__ w,
                                  const float* __restrict__ amp,
                                  const float* __restrict__ phase,
                                  const float* __restrict__ ha,
                                  const float* __restrict__ b,
                                  float* __restrict__ out,
                                  int n) {
    int i = blockIdx.x * blockDim.x + threadIdx.x;
    if (i >= n) return;
    float4 a = g_acc[i];
    g_acc[i] = make_float4(0.0f, 0.0f, 0.0f, 0.0f);  // re-arm for next call
    float xi = x[i];
    float yi = y[i];
    float xe = xi + EPS_C;
    float inv = rsqrtf(xe * xe + yi * yi);
    float s = yi * inv;
    float c = xe * inv;
    float cy = ha[i] * (c * a.x - s * a.y - yi * (c * a.z - s * a.w));
    float r2 = fmaf(xi, xi, fmaf(yi, yi, EPS_C));
    float dy = (MU_C - r2) * yi + w[i] * xi;
    float y_new = fmaf(dy + cy, DT_C, yi);
    float ang = fmaf(amp[i], y_new, phase[i] + b[i]);
    const float BOUND = 1.57079632679489661923f;  // pi/2
    ang = fminf(fmaxf(ang, -BOUND), BOUND);
    out[i] = ang;
}

extern "C" void kernel_launch(void* const* d_in, const int* in_sizes, int n_in,
                              void* d_out, int out_size) {
    const float* x     = (const float*)d_in[0];
    const float* y     = (const float*)d_in[1];
    const float* w     = (const float*)d_in[2];
    const float* amp   = (const float*)d_in[3];
    const float* phase = (const float*)d_in[4];
    const float* ha    = (const float*)d_in[5];
    const float* b     = (const float*)d_in[6];
    const int* edge_src = (const int*)d_in[7];
    const int* edge_dst = (const int*)d_in[8];
    float* out = (float*)d_out;

    int n  = in_sizes[0];
    int ne = in_sizes[7];
    if (n > N_MAX) return;  // scratch sized for the fixed problem

    const int TPB = 256;
    int nodeBlocks = (n + TPB - 1) / TPB;
    node_init_kernel<<<nodeBlocks, TPB>>>(x, y, n);

    // Two half-range edge launches (5x-validated structure; keeps int4
    // alignment; single-launch variant regressed).
    int half = (ne / 2) & ~3;
    {
        int cnt = half;
        int thr = (cnt + 3) / 4;
        int blk = (thr + TPB - 1) / TPB;
        edge_kernel<<<blk, TPB>>>(edge_src, edge_dst, 0, half);
    }
    {
        int cnt = ne - half;
        int thr = (cnt + 3) / 4;
        int blk = (thr + TPB - 1) / TPB;
        edge_kernel<<<blk, TPB>>>(edge_src, edge_dst, half, ne);
    }

    node_final_kernel<<<nodeBlocks, TPB>>>(x, y, w, amp, phase, ha, b, out, n);
}

// round 13
// speedup vs baseline: 1.0195x; 1.0195x over previous
#include <cuda_runtime.h>
#include <math_constants.h>

// Problem constants (fixed by the dataset: n=200,000 nodes, ne=12,800,000 edges)
#define MU_C   1.0f
#define DT_C   0.01f
#define EPS_C  1e-9f
#define N_MAX  262144   // >= 200,000, padded

// Device scratch (no allocations allowed in kernel_launch)
// srcP[j] = { s_j*y_j, c_j*y_j, s_j, c_j }  with s=sin(theta_j), c=cos(theta_j)
// acc[i]  = per-dst sums of srcP over incoming edges (float4 vector atomic)
__device__ float4 g_srcP[N_MAX];
__device__ float4 g_acc[N_MAX];

// ---------------------------------------------------------------------------
// Kernel 1: per-node precompute + accumulator zeroing (scalar, 1 node/thread —
// fastest validated form; vectorized variants and read-and-reset in the
// finalize kernel both regressed).
// s = y/r, c = (x+eps)/r with r = sqrt((x+eps)^2 + y^2)  (== sin/cos of atan2)
// ---------------------------------------------------------------------------
__global__ void node_init_kernel(const float* __restrict__ x,
                                 const float* __restrict__ y,
                                 int n) {
    int i = blockIdx.x * blockDim.x + threadIdx.x;
    if (i >= n) return;
    float xi = x[i];
    float yi = y[i];
    float xe = xi + EPS_C;
    float inv = rsqrtf(xe * xe + yi * yi);
    float s = yi * inv;
    float c = xe * inv;
    g_srcP[i] = make_float4(s * yi, c * yi, s, c);
    g_acc[i] = make_float4(0.0f, 0.0f, 0.0f, 0.0f);
}

// ---------------------------------------------------------------------------
// Kernel 2: edge accumulation over [e0, e1). For edge (j=src -> i=dst):
//   acc[i] += { s_j*y_j, c_j*y_j, s_j, c_j }
// One float4 gather + one float4 vector RED per edge; 4 edges/thread with
// int4 index loads. Five-times-validated optimum — at the diverged-lane-op /
// LTS-RMW floor (~1 cyc gather wavefront + ~1.29 cyc spread REDG per edge/SM).
// ---------------------------------------------------------------------------
__global__ void edge_kernel(const int* __restrict__ edge_src,
                            const int* __restrict__ edge_dst,
                            int e0, int e1) {
    int t = blockIdx.x * blockDim.x + threadIdx.x;
    int base = e0 + t * 4;
    if (base + 3 < e1) {
        int4 si = *reinterpret_cast<const int4*>(edge_src + base);
        int4 di = *reinterpret_cast<const int4*>(edge_dst + base);
        float4 p0 = __ldg(&g_srcP[si.x]);
        float4 p1 = __ldg(&g_srcP[si.y]);
        float4 p2 = __ldg(&g_srcP[si.z]);
        float4 p3 = __ldg(&g_srcP[si.w]);
        atomicAdd(&g_acc[di.x], p0);
        atomicAdd(&g_acc[di.y], p1);
        atomicAdd(&g_acc[di.z], p2);
        atomicAdd(&g_acc[di.w], p3);
    } else if (base < e1) {
        for (int e = base; e < e1; e++) {
            float4 p = __ldg(&g_srcP[edge_src[e]]);
            atomicAdd(&g_acc[edge_dst[e]], p);
        }
    }
}

// ---------------------------------------------------------------------------
// Kernel 3: finalize (scalar, 1 node/thread — fastest validated form).
//   cy_i = ha_i * [ c_i*A - s_i*B - y_i*(c_i*C - s_i*D) ],  acc[i]={A,B,C,D}
//   dy   = (MU - r2)*y + w*x ; y_new = y + (dy + cy)*DT
//   angles = clip(amp*y_new + phase + b, -pi/2, pi/2)
// (dx / x_new are dead code: the output depends only on y_new.)
// ---------------------------------------------------------------------------
__global__ void node_final_kernel(const float* __restrict__ x,
                                  const float* __restrict__ y,
                                  const float* __restrict__ w,
                                  const float* __restrict__ amp,
                                  const float* __restrict__ phase,
                                  const float* __restrict__ ha,
                                  const float* __restrict__ b,
                                  float* __restrict__ out,
                                  int n) {
    int i = blockIdx.x * blockDim.x + threadIdx.x;
    if (i >= n) return;
    float xi = x[i];
    float yi = y[i];
    float xe = xi + EPS_C;
    float inv = rsqrtf(xe * xe + yi * yi);
    float s = yi * inv;
    float c = xe * inv;
    float4 a = g_acc[i];
    float cy = ha[i] * (c * a.x - s * a.y - yi * (c * a.z - s * a.w));
    float r2 = fmaf(xi, xi, fmaf(yi, yi, EPS_C));
    float dy = (MU_C - r2) * yi + w[i] * xi;
    float y_new = fmaf(dy + cy, DT_C, yi);
    float ang = fmaf(amp[i], y_new, phase[i] + b[i]);
    const float BOUND = 1.57079632679489661923f;  // pi/2
    ang = fminf(fmaxf(ang, -BOUND), BOUND);
    out[i] = ang;
}

extern "C" void kernel_launch(void* const* d_in, const int* in_sizes, int n_in,
                              void* d_out, int out_size) {
    const float* x     = (const float*)d_in[0];
    const float* y     = (const float*)d_in[1];
    const float* w     = (const float*)d_in[2];
    const float* amp   = (const float*)d_in[3];
    const float* phase = (const float*)d_in[4];
    const float* ha    = (const float*)d_in[5];
    const float* b     = (const float*)d_in[6];
    const int* edge_src = (const int*)d_in[7];
    const int* edge_dst = (const int*)d_in[8];
    float* out = (float*)d_out;

    int n  = in_sizes[0];
    int ne = in_sizes[7];
    if (n > N_MAX) return;  // scratch sized for the fixed problem

    const int TPB = 256;
    int nodeBlocks = (n + TPB - 1) / TPB;
    node_init_kernel<<<nodeBlocks, TPB>>>(x, y, n);

    // Two half-range edge launches (five-times-validated structure; keeps
    // int4 alignment; single-launch variant regressed).
    int half = (ne / 2) & ~3;
    {
        int cnt = half;
        int thr = (cnt + 3) / 4;
        int blk = (thr + TPB - 1) / TPB;
        edge_kernel<<<blk, TPB>>>(edge_src, edge_dst, 0, half);
    }
    {
        int cnt = ne - half;
        int thr = (cnt + 3) / 4;
        int blk = (thr + TPB - 1) / TPB;
        edge_kernel<<<blk, TPB>>>(edge_src, edge_dst, half, ne);
    }

    node_final_kernel<<<nodeBlocks, TPB>>>(x, y, w, amp, phase, ha, b, out, n);
}